// round 8
// baseline (speedup 1.0000x reference)
#include <cuda_runtime.h>
#include <cstdint>

// Graph_Learn fused, stage-free. S[b,t,i,j] = exp(relu(sum_f a_f*|xi-xj|))/rowsum
// (row sum == reference column sum by exact bitwise symmetry).
// Thread = column j. xj chunks via per-thread LDG.128; xi rows via warp-uniform
// LDG.128 broadcast. Subtraction fused as fma(xj, -1x2, xi). No smem staging.

#define Vn 256
#define Fn 64
#define Rr 8

typedef unsigned long long u64;

__device__ __forceinline__ u64 f2add(u64 a, u64 b) {
    u64 d; asm("add.rn.f32x2 %0,%1,%2;" : "=l"(d) : "l"(a), "l"(b)); return d;
}
__device__ __forceinline__ u64 f2fma(u64 a, u64 b, u64 c) {
    u64 d; asm("fma.rn.f32x2 %0,%1,%2,%3;" : "=l"(d) : "l"(a), "l"(b), "l"(c)); return d;
}
__device__ __forceinline__ u64 f2abs(u64 a) {
    u64 d; asm("and.b64 %0,%1,0x7FFFFFFF7FFFFFFF;" : "=l"(d) : "l"(a)); return d;
}
__device__ __forceinline__ u64 packf2(float lo, float hi) {
    u64 d; asm("mov.b64 %0,{%1,%2};" : "=l"(d) : "f"(lo), "f"(hi)); return d;
}
__device__ __forceinline__ void unpackf2(u64 v, float& lo, float& hi) {
    asm("mov.b64 {%0,%1},%2;" : "=f"(lo), "=f"(hi) : "l"(v));
}

__global__ __launch_bounds__(256, 4)
void gl_kernel(const float* __restrict__ x, const float* __restrict__ a,
               float* __restrict__ out)
{
    __shared__ float wsum[Rr * 8];
    __shared__ float rdn[Rr];

    const int tid = threadIdx.x;
    const int i0  = blockIdx.x * Rr;     // row tile (fast dim -> co-resident
    const int bt  = blockIdx.y;          //   blocks share the same bt slice)
    const int j   = tid;

    const float* xb = x + (size_t)bt * Vn * Fn;
    const u64 NEG1 = packf2(-1.0f, -1.0f);

    u64 acc[Rr];
    #pragma unroll
    for (int r = 0; r < Rr; ++r) acc[r] = 0ull;

    #pragma unroll 1
    for (int c = 0; c < 4; ++c) {
        const int f0 = c << 4;

        // xj chunk: 4x LDG.128 (per-thread row, L1/L2-hot across blocks)
        u64 xj[8];
        {
            const ulonglong2* xr = (const ulonglong2*)(xb + j * Fn + f0);
            ulonglong2 q0 = xr[0], q1 = xr[1], q2 = xr[2], q3 = xr[3];
            xj[0] = q0.x; xj[1] = q0.y; xj[2] = q1.x; xj[3] = q1.y;
            xj[4] = q2.x; xj[5] = q2.y; xj[6] = q3.x; xj[7] = q3.y;
        }
        // a chunk: warp-uniform LDG.128
        u64 av[8];
        {
            const ulonglong2* ar = (const ulonglong2*)(a + f0);
            ulonglong2 q0 = ar[0], q1 = ar[1], q2 = ar[2], q3 = ar[3];
            av[0] = q0.x; av[1] = q0.y; av[2] = q1.x; av[3] = q1.y;
            av[4] = q2.x; av[5] = q2.y; av[6] = q3.x; av[7] = q3.y;
        }

        #pragma unroll
        for (int r = 0; r < Rr; ++r) {
            // xi row chunk: warp-uniform LDG.128 broadcast (1 sector each)
            const ulonglong2* ir = (const ulonglong2*)(xb + (i0 + r) * Fn + f0);
            ulonglong2 u0 = ir[0], u1 = ir[1], u2 = ir[2], u3 = ir[3];
            u64 xi[8];
            xi[0] = u0.x; xi[1] = u0.y; xi[2] = u1.x; xi[3] = u1.y;
            xi[4] = u2.x; xi[5] = u2.y; xi[6] = u3.x; xi[7] = u3.y;

            u64 s = acc[r];
            #pragma unroll
            for (int k = 0; k < 8; ++k) {
                u64 d = f2fma(xj[k], NEG1, xi[k]);   // xi - xj (FFMA2)
                d = f2abs(d);                        // 2x LOP3
                s = f2fma(d, av[k], s);              // FFMA2
            }
            acc[r] = s;
        }
    }

    // tmpS = exp(relu(lo+hi))
    float f[Rr];
    #pragma unroll
    for (int r = 0; r < Rr; ++r) {
        float lo, hi;
        unpackf2(acc[r], lo, hi);
        f[r] = __expf(fmaxf(lo + hi, 0.f));
    }

    // denom: row sums (== column sums by exact symmetry)
    const int lane = tid & 31, w = tid >> 5;
    #pragma unroll
    for (int r = 0; r < Rr; ++r) {
        float v = f[r];
        v += __shfl_xor_sync(0xffffffffu, v, 16);
        v += __shfl_xor_sync(0xffffffffu, v, 8);
        v += __shfl_xor_sync(0xffffffffu, v, 4);
        v += __shfl_xor_sync(0xffffffffu, v, 2);
        v += __shfl_xor_sync(0xffffffffu, v, 1);
        if (lane == 0) wsum[r * 8 + w] = v;
    }
    __syncthreads();
    if (tid < Rr) {
        float d = 0.f;
        #pragma unroll
        for (int q = 0; q < 8; ++q) d += wsum[tid * 8 + q];
        rdn[tid] = __fdividef(1.0f, d);
    }
    __syncthreads();

    float* op = out + ((size_t)bt * Vn + i0) * Vn + j;
    #pragma unroll
    for (int r = 0; r < Rr; ++r)
        op[(size_t)r * Vn] = f[r] * rdn[r];
}

extern "C" void kernel_launch(void* const* d_in, const int* in_sizes, int n_in,
                              void* d_out, int out_size)
{
    const float* x = (const float*)d_in[0];
    const float* a = (const float*)d_in[1];
    if (n_in >= 2 && in_sizes[0] == Fn && in_sizes[1] > Fn) {
        x = (const float*)d_in[1];
        a = (const float*)d_in[0];
    }
    int bt = in_sizes[0] == Fn ? in_sizes[1] / (Vn * Fn) : in_sizes[0] / (Vn * Fn);

    dim3 grid(Vn / Rr, bt);
    gl_kernel<<<grid, 256>>>(x, a, (float*)d_out);
}

// round 9
// speedup vs baseline: 1.4012x; 1.4012x over previous
#include <cuda_runtime.h>
#include <cstdint>

// Graph_Learn: single-launch software-pipelined triangle scheme.
// K1-role blocks (bids < nK1): compute tmpS = exp(relu(sum_f a_f*|xi-xj|)) on a
//   trapezoid tile-pair, write direct + mirror to scratch (bitwise-exact
//   symmetry), then release-publish per-bt completion counter.
// K2-role blocks (bids >= nK1): acquire-spin until their bt's 32 K1 blocks are
//   done, then warp-per-row normalize (row sum == reference column sum by
//   symmetry) scratch -> out. K2 overlaps with later-bt K1 work.

#define Vn 256
#define Fn 64
#define TR 4
#define PAD 68          // floats per smem row (17 * 16B, odd quad stride)

#define SMEM_AS   (Vn * PAD)          // a[64] after the slice
#define SMEM_FLOATS (SMEM_AS + Fn)
#define SMEM_BYTES  (SMEM_FLOATS * 4)

typedef unsigned long long u64;

__device__ float g_tmp[32u * Vn * Vn];   // 8 MB scratch (BT <= 32)
__device__ int   g_cnt[32];              // K1-done counters (self-resetting)
__device__ int   g_fin[32];              // K2-done counters (self-resetting)

__device__ __forceinline__ u64 f2add(u64 a, u64 b) {
    u64 d; asm("add.rn.f32x2 %0,%1,%2;" : "=l"(d) : "l"(a), "l"(b)); return d;
}
__device__ __forceinline__ u64 f2fma(u64 a, u64 b, u64 c) {
    u64 d; asm("fma.rn.f32x2 %0,%1,%2,%3;" : "=l"(d) : "l"(a), "l"(b), "l"(c)); return d;
}
__device__ __forceinline__ u64 f2abs(u64 a) {
    u64 d; asm("and.b64 %0,%1,0x7FFFFFFF7FFFFFFF;" : "=l"(d) : "l"(a)); return d;
}
__device__ __forceinline__ u64 packf2(float lo, float hi) {
    u64 d; asm("mov.b64 %0,{%1,%2};" : "=l"(d) : "f"(lo), "f"(hi)); return d;
}
__device__ __forceinline__ void unpackf2(u64 v, float& lo, float& hi) {
    asm("mov.b64 {%0,%1},%2;" : "=f"(lo), "=f"(hi) : "l"(v));
}
__device__ __forceinline__ void lds_2x64(uint32_t addr, u64& p0, u64& p1) {
    asm volatile("ld.shared.v2.u64 {%0,%1},[%2];" : "=l"(p0), "=l"(p1) : "r"(addr));
}
__device__ __forceinline__ int ld_acq(const int* p) {
    int v; asm volatile("ld.acquire.gpu.b32 %0,[%1];" : "=r"(v) : "l"(p) : "memory");
    return v;
}

__device__ __forceinline__ void tile_rows(uint32_t xs_sh, int i0, int f0,
                                          const u64* nxj, const u64* av, u64* acc)
{
    #pragma unroll
    for (int r = 0; r < TR; ++r) {
        const uint32_t base = xs_sh + (uint32_t)(((i0 + r) * PAD + f0) * 4);
        u64 xi[8];
        lds_2x64(base +  0, xi[0], xi[1]);   // uniform broadcast LDS.128
        lds_2x64(base + 16, xi[2], xi[3]);
        lds_2x64(base + 32, xi[4], xi[5]);
        lds_2x64(base + 48, xi[6], xi[7]);
        u64 s = acc[r];
        #pragma unroll
        for (int k = 0; k < 8; ++k) {
            u64 d = f2abs(f2add(xi[k], nxj[k]));   // ADD2 + 2xLOP3
            s = f2fma(d, av[k], s);                // FFMA2
        }
        acc[r] = s;
    }
}

__device__ __forceinline__ void store_tile(const u64* acc, int bt, int i0, int j)
{
    float f[TR];
    #pragma unroll
    for (int r = 0; r < TR; ++r) {
        float lo, hi; unpackf2(acc[r], lo, hi);
        f[r] = __expf(fmaxf(lo + hi, 0.f));
    }
    float* base = g_tmp + ((size_t)bt * Vn + i0) * Vn + j;
    #pragma unroll
    for (int r = 0; r < TR; ++r)
        base[(size_t)r * Vn] = f[r];                      // direct (coalesced)
    // mirror: one aligned float4 per thread -> full 32B sector
    *(float4*)(g_tmp + ((size_t)bt * Vn + j) * Vn + i0) =
        make_float4(f[0], f[1], f[2], f[3]);
}

__global__ __launch_bounds__(256, 3)
void gl_fused(const float* __restrict__ x, const float* __restrict__ a,
              float* __restrict__ out, int nK1)
{
    const int bid = blockIdx.x;
    const int tid = threadIdx.x;

    if (bid < nK1) {
        // ================= K1 role =================
        extern __shared__ float sm[];
        float* xs  = sm;
        float* as_ = sm + SMEM_AS;

        const int bt = bid >> 5;            // bt-major: groups complete in order
        const int k  = bid & 31;
        const int iA = k * TR;
        const int iB = (Vn - TR) - k * TR;

        const float4* xp = (const float4*)(x + (size_t)bt * Vn * Fn);
        #pragma unroll
        for (int it = 0; it < 16; ++it) {
            int kk = tid + it * 256;
            float4 v = xp[kk];
            int row = kk >> 4, fc = (kk & 15) << 2;
            *(float4*)&xs[row * PAD + fc] = v;
        }
        if (tid < Fn) as_[tid] = a[tid];
        __syncthreads();

        const int wid = tid >> 5;
        const bool actA = ((wid + 1) << 5) > iA;    // warp-uniform
        const bool actB = ((wid + 1) << 5) > iB;

        const uint32_t xs_sh = (uint32_t)__cvta_generic_to_shared(xs);
        const uint32_t as_sh = (uint32_t)__cvta_generic_to_shared(as_);
        const int j = tid;

        u64 accA[TR] = {0,0,0,0}, accB[TR] = {0,0,0,0};

        if (actA | actB) {
            #pragma unroll 1
            for (int c = 0; c < 4; ++c) {
                const int f0 = c << 4;
                u64 nxj[8], av[8];
                {
                    const uint32_t jb = xs_sh + (uint32_t)((j * PAD + f0) * 4);
                    u64 t[8];
                    lds_2x64(jb +  0, t[0], t[1]);
                    lds_2x64(jb + 16, t[2], t[3]);
                    lds_2x64(jb + 32, t[4], t[5]);
                    lds_2x64(jb + 48, t[6], t[7]);
                    #pragma unroll
                    for (int q = 0; q < 8; ++q) {
                        float lo, hi; unpackf2(t[q], lo, hi);
                        nxj[q] = packf2(-lo, -hi);
                    }
                    const uint32_t ab = as_sh + (uint32_t)(f0 * 4);
                    lds_2x64(ab +  0, av[0], av[1]);
                    lds_2x64(ab + 16, av[2], av[3]);
                    lds_2x64(ab + 32, av[4], av[5]);
                    lds_2x64(ab + 48, av[6], av[7]);
                }
                if (actA) tile_rows(xs_sh, iA, f0, nxj, av, accA);
                if (actB) tile_rows(xs_sh, iB, f0, nxj, av, accB);
            }
        }

        if (actA) store_tile(accA, bt, iA, j);
        if (actB) store_tile(accB, bt, iB, j);

        // release: all block stores visible, then count this block done
        __syncthreads();
        if (tid == 0) {
            __threadfence();
            atomicAdd(&g_cnt[bt], 1);
        }
    } else {
        // ================= K2 role =================
        const int idx = bid - nK1;
        const int bt  = idx >> 5;
        const int blk = idx & 31;           // 8 rows per block

        if (tid == 0) {
            while (ld_acq(&g_cnt[bt]) < 32) __nanosleep(64);
        }
        __syncthreads();                     // acquire published to whole block

        const int lane = tid & 31, w = tid >> 5;
        const int row  = blk * 8 + w;

        const float4* rp = (const float4*)(g_tmp + ((size_t)bt * Vn + row) * Vn);
        float4 v0 = __ldcg(rp + lane);       // L2-coherent reads
        float4 v1 = __ldcg(rp + lane + 32);

        float s = ((v0.x + v0.y) + (v0.z + v0.w)) + ((v1.x + v1.y) + (v1.z + v1.w));
        s += __shfl_xor_sync(0xffffffffu, s, 16);
        s += __shfl_xor_sync(0xffffffffu, s, 8);
        s += __shfl_xor_sync(0xffffffffu, s, 4);
        s += __shfl_xor_sync(0xffffffffu, s, 2);
        s += __shfl_xor_sync(0xffffffffu, s, 1);
        const float rc = __fdividef(1.0f, s);

        v0.x *= rc; v0.y *= rc; v0.z *= rc; v0.w *= rc;
        v1.x *= rc; v1.y *= rc; v1.z *= rc; v1.w *= rc;

        float4* op = (float4*)(out + ((size_t)bt * Vn + row) * Vn);
        op[lane]      = v0;
        op[lane + 32] = v1;

        // self-reset counters for the next graph replay (last K2 block of bt)
        __syncthreads();
        if (tid == 0) {
            int f = atomicAdd(&g_fin[bt], 1);
            if (f == 31) {
                g_cnt[bt] = 0;
                __threadfence();
                g_fin[bt] = 0;
            }
        }
    }
}

extern "C" void kernel_launch(void* const* d_in, const int* in_sizes, int n_in,
                              void* d_out, int out_size)
{
    const float* x = (const float*)d_in[0];
    const float* a = (const float*)d_in[1];
    if (n_in >= 2 && in_sizes[0] == Fn && in_sizes[1] > Fn) {
        x = (const float*)d_in[1];
        a = (const float*)d_in[0];
    }
    int bt = in_sizes[0] == Fn ? in_sizes[1] / (Vn * Fn) : in_sizes[0] / (Vn * Fn);

    cudaFuncSetAttribute(gl_fused, cudaFuncAttributeMaxDynamicSharedMemorySize,
                         SMEM_BYTES);
    const int nK1 = bt * 32;                 // trapezoid-pair blocks (bt-major)
    const int nK2 = bt * 32;                 // normalize blocks (8 rows each)
    gl_fused<<<nK1 + nK2, 256, SMEM_BYTES>>>(x, a, (float*)d_out, nK1);
}